// round 13
// baseline (speedup 1.0000x reference)
#include <cuda_runtime.h>

#define N 384
#define D 256
#define EPSF 1e-12f
#define NTILES 21
#define NUNITS (NTILES * N)   // 8064
#define NBLK 296              // 148 SMs x 2 blocks, all co-resident
#define NGRAMH 288            // gram half-tiles: 2 sides x 2 D-halves x 72
#define NPREP 288             // prep blocks: 73728 float4 items / 256
#define BI 8                  // i-batch staged in smem

typedef unsigned long long u64;

// scratch (no allocation allowed)
__device__ float  g_Gh[4][N * N];  // [z*2+half] partial grams
__device__ float  g_dj[2][2][N];   // per-side, per-half diagonal partials
__device__ float  g_Gs[N * N];
__device__ float  g_Gt[N * N];
__device__ float  g_ps[N * N];     // p_s
__device__ float  g_cps[N * N];    // (Gs_ii - Gs_ij) * p_s
__device__ float  g_nrqs[N * N];   // -Gs_ij * p_s
__device__ float  g_pt[N * N];     // p_t (j-side)
__device__ float  g_cpt[N * N];    // (Gt_ii - Gt_ij) * p_t
__device__ float  g_qtn[N * N];    // -p_t   (k-side, negated)
__device__ float  g_ntn[N * N];    // +Gt_ij * p_t  (= -nr_t, k-side negated)
__device__ double g_sum;
__device__ int    g_cnt;
__device__ int    g_bar1;
__device__ int    g_bar2;

// upper-triangle 64x64 tile enumeration (a <= b), 21 tiles over a 6x6 grid
__constant__ int c_TA[NTILES] = {0,0,0,0,0,0,1,1,1,1,1,2,2,2,2,3,3,3,4,4,5};
__constant__ int c_TB[NTILES] = {0,1,2,3,4,5,1,2,3,4,5,2,3,4,5,3,4,5,4,5,5};

// ---------------------------------------------------------------------------
// packed f32x2 helpers (sm_103a)
__device__ __forceinline__ u64 pk(float lo, float hi) {
    union { float2 f; u64 u; } t; t.f.x = lo; t.f.y = hi; return t.u;
}
__device__ __forceinline__ float2 upk(u64 v) {
    union { float2 f; u64 u; } t; t.u = v; return t.f;
}
union F4U2 { float4 f; ulonglong2 u; };

__device__ __forceinline__ u64 mul2(u64 a, u64 b) {
    u64 r; asm("mul.rn.f32x2 %0,%1,%2;" : "=l"(r) : "l"(a), "l"(b)); return r;
}
__device__ __forceinline__ u64 fma2(u64 a, u64 b, u64 c) {
    u64 r; asm("fma.rn.f32x2 %0,%1,%2,%3;" : "=l"(r) : "l"(a), "l"(b), "l"(c)); return r;
}

// smem buffer shared by phases
#define SM_AS 0                      // 2*32*34*4 = 8704
#define SM_BS 8704                   // 2*32*68*4 = 17408 -> 26112
#define SM_STAGE 0                   // 8*BI*64*4 = 16384
#define SM_RED 16384                 // 256*4
#define SM_BYTES 26624

// ---------------------------------------------------------------------------
__global__ void __launch_bounds__(256, 2) rkd_fused_kernel(const float* __restrict__ S,
                                                           const float* __restrict__ T,
                                                           float* __restrict__ out) {
    __shared__ __align__(16) char smbuf[SM_BYTES];

    int tid = threadIdx.x;
    int b = blockIdx.x;

    // =======================================================================
    // Phase A: partial grams (blocks 0..287: side z, D-half, 32x64 tile)
    // =======================================================================
    if (b < NGRAMH) {
        int z = b / 144;
        int r0 = b - z * 144;
        int half = r0 / 72;
        int q = r0 - half * 72;
        int bx = q % 6;            // k-tile (64 wide)
        int by = q / 6;            // j-tile (32 tall)

        const float* __restrict__ E = (z == 0) ? S : T;
        float* __restrict__ GH = g_Gh[z * 2 + half];

        typedef float (*AsT)[32][34];
        typedef float (*BsT)[32][68];
        AsT As = (AsT)(smbuf + SM_AS);
        BsT Bs = (BsT)(smbuf + SM_BS);

        if (b == 0 && tid == 0) g_sum = 0.0;

        int ty = tid >> 4, tx = tid & 15;
        int row = tid >> 3;
        int c4 = (tid & 7) * 4;

        int tj = by * 32, tk = bx * 64;
        int dk = half * 128;       // D-half offset

        const float* pA  = &E[(tj + row) * D + dk + c4];
        const float* pB0 = &E[(tk + row) * D + dk + c4];
        const float* pB1 = &E[(tk + 32 + row) * D + dk + c4];

        float acc[2][4];
#pragma unroll
        for (int r = 0; r < 2; r++)
#pragma unroll
            for (int c = 0; c < 4; c++) acc[r][c] = 0.f;

        float ssA = 0.f;

        float4 av  = *reinterpret_cast<const float4*>(pA);
        float4 bv0 = *reinterpret_cast<const float4*>(pB0);
        float4 bv1 = *reinterpret_cast<const float4*>(pB1);
        As[0][c4 + 0][row] = av.x;  As[0][c4 + 1][row] = av.y;
        As[0][c4 + 2][row] = av.z;  As[0][c4 + 3][row] = av.w;
        Bs[0][c4 + 0][row] = bv0.x; Bs[0][c4 + 1][row] = bv0.y;
        Bs[0][c4 + 2][row] = bv0.z; Bs[0][c4 + 3][row] = bv0.w;
        Bs[0][c4 + 0][row + 32] = bv1.x; Bs[0][c4 + 1][row + 32] = bv1.y;
        Bs[0][c4 + 2][row + 32] = bv1.z; Bs[0][c4 + 3][row + 32] = bv1.w;
        ssA = fmaf(av.x, av.x, fmaf(av.y, av.y, fmaf(av.z, av.z, fmaf(av.w, av.w, ssA))));
        __syncthreads();

#pragma unroll
        for (int chunk = 0; chunk < 4; chunk++) {
            int cur = chunk & 1;
            bool more = (chunk < 3);
            if (more) {
                int off = (chunk + 1) * 32;
                av  = *reinterpret_cast<const float4*>(pA  + off);
                bv0 = *reinterpret_cast<const float4*>(pB0 + off);
                bv1 = *reinterpret_cast<const float4*>(pB1 + off);
            }
#pragma unroll
            for (int kk = 0; kk < 32; kk++) {
                float2 a2 = *reinterpret_cast<const float2*>(&As[cur][kk][ty * 2]);
                float4 b4 = *reinterpret_cast<const float4*>(&Bs[cur][kk][tx * 4]);
                acc[0][0] = fmaf(a2.x, b4.x, acc[0][0]);
                acc[0][1] = fmaf(a2.x, b4.y, acc[0][1]);
                acc[0][2] = fmaf(a2.x, b4.z, acc[0][2]);
                acc[0][3] = fmaf(a2.x, b4.w, acc[0][3]);
                acc[1][0] = fmaf(a2.y, b4.x, acc[1][0]);
                acc[1][1] = fmaf(a2.y, b4.y, acc[1][1]);
                acc[1][2] = fmaf(a2.y, b4.z, acc[1][2]);
                acc[1][3] = fmaf(a2.y, b4.w, acc[1][3]);
            }
            if (more) {
                int nb = cur ^ 1;
                As[nb][c4 + 0][row] = av.x;  As[nb][c4 + 1][row] = av.y;
                As[nb][c4 + 2][row] = av.z;  As[nb][c4 + 3][row] = av.w;
                Bs[nb][c4 + 0][row] = bv0.x; Bs[nb][c4 + 1][row] = bv0.y;
                Bs[nb][c4 + 2][row] = bv0.z; Bs[nb][c4 + 3][row] = bv0.w;
                Bs[nb][c4 + 0][row + 32] = bv1.x; Bs[nb][c4 + 1][row + 32] = bv1.y;
                Bs[nb][c4 + 2][row + 32] = bv1.z; Bs[nb][c4 + 3][row + 32] = bv1.w;
                ssA = fmaf(av.x, av.x, fmaf(av.y, av.y, fmaf(av.z, av.z, fmaf(av.w, av.w, ssA))));
            }
            __syncthreads();
        }

        // diag partial: sum-of-squares of this D-half for the 32 j-rows
#pragma unroll
        for (int m = 4; m > 0; m >>= 1)
            ssA += __shfl_xor_sync(0xffffffffu, ssA, m, 8);
        if (bx == 0 && (tid & 7) == 0)
            g_dj[z][half][tj + row] = ssA;

        int jg = tj + ty * 2;
        int kg = tk + tx * 4;
#pragma unroll
        for (int r = 0; r < 2; r++)
            *reinterpret_cast<float4*>(&GH[(jg + r) * N + kg]) =
                make_float4(acc[r][0], acc[r][1], acc[r][2], acc[r][3]);

        __syncthreads();
    }

    // barrier 1 ----------------------------------------------------------
    if (tid == 0) {
        __threadfence();
        atomicAdd(&g_bar1, 1);
        while (*((volatile int*)&g_bar1) < NBLK) __nanosleep(32);
        __threadfence();
    }
    __syncthreads();

    // =======================================================================
    // Phase B: prep (blocks 0..287, 256 float4 items each)
    // =======================================================================
    if (b < NPREP) {
        int g = b * 256 + tid;      // 0..73727
        int z = g / 36864;
        int gi = g - z * 36864;
        int idx = gi * 4;
        int i = idx / N;
        int j0 = idx - i * N;

        const float* GH0 = g_Gh[z * 2 + 0];
        const float* GH1 = g_Gh[z * 2 + 1];

        float4 g0 = *reinterpret_cast<const float4*>(&GH0[idx]);
        float4 g1 = *reinterpret_cast<const float4*>(&GH1[idx]);
        float4 dj0 = *reinterpret_cast<const float4*>(&g_dj[z][0][j0]);
        float4 dj1 = *reinterpret_cast<const float4*>(&g_dj[z][1][j0]);
        float di = g_dj[z][0][i] + g_dj[z][1][i];

        float gv[4] = {g0.x + g1.x, g0.y + g1.y, g0.z + g1.z, g0.w + g1.w};
        float djv[4] = {dj0.x + dj1.x, dj0.y + dj1.y, dj0.z + dj1.z, dj0.w + dj1.w};

        float p[4], cp[4], nr[4];
#pragma unroll
        for (int c = 0; c < 4; c++) {
            float cs = di - gv[c];
            float n2 = fmaxf((djv[c] - gv[c]) + cs, 0.f);
            float pv = (i == j0 + c) ? 0.f : (1.f / fmaxf(sqrtf(n2), EPSF));
            p[c] = pv;
            cp[c] = cs * pv;
            nr[c] = -gv[c] * pv;
        }

        float4 gvv = make_float4(gv[0], gv[1], gv[2], gv[3]);
        float4 pv4 = make_float4(p[0], p[1], p[2], p[3]);
        float4 cp4 = make_float4(cp[0], cp[1], cp[2], cp[3]);
        if (z == 0) {
            *reinterpret_cast<float4*>(&g_Gs[idx])   = gvv;
            *reinterpret_cast<float4*>(&g_ps[idx])   = pv4;
            *reinterpret_cast<float4*>(&g_cps[idx])  = cp4;
            *reinterpret_cast<float4*>(&g_nrqs[idx]) = make_float4(nr[0], nr[1], nr[2], nr[3]);
        } else {
            *reinterpret_cast<float4*>(&g_Gt[idx])  = gvv;
            *reinterpret_cast<float4*>(&g_pt[idx])  = pv4;
            *reinterpret_cast<float4*>(&g_cpt[idx]) = cp4;
            *reinterpret_cast<float4*>(&g_qtn[idx]) = make_float4(-p[0], -p[1], -p[2], -p[3]);
            *reinterpret_cast<float4*>(&g_ntn[idx]) = make_float4(-nr[0], -nr[1], -nr[2], -nr[3]);
        }
    }

    // barrier 2 ----------------------------------------------------------
    if (tid == 0) {
        __threadfence();
        atomicAdd(&g_bar2, 1);
        while (*((volatile int*)&g_bar2) < NBLK) __nanosleep(32);
        __threadfence();
    }
    __syncthreads();

    // =======================================================================
    // Phase C: angle loss (all blocks). 6-packed-op math via negated teacher.
    //   d = qs*(ps*Gs+cps) + qtn*(pt*Gt+cpt) + (ntn*pt + ns*ps)
    // =======================================================================
    typedef float (*StT)[BI][64];
    StT stage = (StT)(smbuf + SM_STAGE);
    float* red = (float*)(smbuf + SM_RED);

    int ty = tid >> 4, tx = tid & 15;

    int jl_col4 = (tid & 15) * 4;
    int l_ii    = (tid >> 4) & 7;
    int l_hi    = tid >> 7;

    int u0 = (b * NUNITS) / NBLK;
    int u1 = ((b + 1) * NUNITS) / NBLK;
    int tile = u0 / N;
    int i = u0 - tile * N;
    int remaining = u1 - u0;

    float wacc = 0.f;

    while (remaining > 0) {
        int cnt = min(N - i, remaining);
        remaining -= cnt;

        int tj = c_TA[tile] * 64;
        int tk = c_TB[tile] * 64;
        int jq = tj + ty * 4;
        int kq = tk + tx * 4;

        const float* src0 = (l_hi ? g_cps  + tj : g_ps  + tj) + jl_col4;  // st 0/1
        const float* src1 = (l_hi ? g_nrqs + tk : g_ps  + tk) + jl_col4;  // st 2/3
        const float* src2 = (l_hi ? g_cpt  + tj : g_pt  + tj) + jl_col4;  // st 4/5
        const float* src3 = (l_hi ? g_ntn  + tk : g_qtn + tk) + jl_col4;  // st 6/7

        // G microtile packed along k (free reinterpret of LDG.128)
        u64 G2s[4][2], G2t[4][2];
#pragma unroll
        for (int jj = 0; jj < 4; jj++) {
            ulonglong2 vs = *reinterpret_cast<const ulonglong2*>(&g_Gs[(jq + jj) * N + kq]);
            ulonglong2 vt = *reinterpret_cast<const ulonglong2*>(&g_Gt[(jq + jj) * N + kq]);
            G2s[jj][0] = vs.x; G2s[jj][1] = vs.y;
            G2t[jj][0] = vt.x; G2t[jj][1] = vt.y;
        }

        float acc0 = 0.f, acc1 = 0.f;

        for (int s = 0; s < cnt; s += BI) {
            {
                int ir = min(i + s + l_ii, N - 1) * N;
                float4 v0 = *reinterpret_cast<const float4*>(src0 + ir);
                float4 v1 = *reinterpret_cast<const float4*>(src1 + ir);
                float4 v2 = *reinterpret_cast<const float4*>(src2 + ir);
                float4 v3 = *reinterpret_cast<const float4*>(src3 + ir);
                *reinterpret_cast<float4*>(&stage[0 + l_hi][l_ii][jl_col4]) = v0;
                *reinterpret_cast<float4*>(&stage[2 + l_hi][l_ii][jl_col4]) = v1;
                *reinterpret_cast<float4*>(&stage[4 + l_hi][l_ii][jl_col4]) = v2;
                *reinterpret_cast<float4*>(&stage[6 + l_hi][l_ii][jl_col4]) = v3;
            }
            __syncthreads();

            int bi = min(BI, cnt - s);
            for (int ii = 0; ii < bi; ii++) {
                float4 pj_s = *reinterpret_cast<const float4*>(&stage[0][ii][ty * 4]);
                float4 cj_s = *reinterpret_cast<const float4*>(&stage[1][ii][ty * 4]);
                F4U2 qk_s;  qk_s.f  = *reinterpret_cast<const float4*>(&stage[2][ii][tx * 4]);
                F4U2 nr_s;  nr_s.f  = *reinterpret_cast<const float4*>(&stage[3][ii][tx * 4]);
                float4 pj_t = *reinterpret_cast<const float4*>(&stage[4][ii][ty * 4]);
                float4 cj_t = *reinterpret_cast<const float4*>(&stage[5][ii][ty * 4]);
                F4U2 qk_tn; qk_tn.f = *reinterpret_cast<const float4*>(&stage[6][ii][tx * 4]);
                F4U2 nr_tn; nr_tn.f = *reinterpret_cast<const float4*>(&stage[7][ii][tx * 4]);

                u64 q2s[2]  = { qk_s.u.x,  qk_s.u.y  };
                u64 n2s[2]  = { nr_s.u.x,  nr_s.u.y  };
                u64 q2tn[2] = { qk_tn.u.x, qk_tn.u.y };
                u64 n2tn[2] = { nr_tn.u.x, nr_tn.u.y };

                float pjs_a[4] = {pj_s.x, pj_s.y, pj_s.z, pj_s.w};
                float cjs_a[4] = {cj_s.x, cj_s.y, cj_s.z, cj_s.w};
                float pjt_a[4] = {pj_t.x, pj_t.y, pj_t.z, pj_t.w};
                float cjt_a[4] = {cj_t.x, cj_t.y, cj_t.z, cj_t.w};

#pragma unroll
                for (int jj = 0; jj < 4; jj++) {
                    u64 p2s = pk(pjs_a[jj], pjs_a[jj]);
                    u64 c2s = pk(cjs_a[jj], cjs_a[jj]);
                    u64 p2t = pk(pjt_a[jj], pjt_a[jj]);
                    u64 c2t = pk(cjt_a[jj], cjt_a[jj]);
#pragma unroll
                    for (int p = 0; p < 2; p++) {
                        u64 t2s = fma2(p2s, G2s[jj][p], c2s);
                        u64 t2t = fma2(p2t, G2t[jj][p], c2t);
                        u64 m   = mul2(n2s[p], p2s);
                        u64 m2  = fma2(n2tn[p], p2t, m);
                        u64 e   = fma2(q2tn[p], t2t, m2);
                        u64 d2  = fma2(q2s[p], t2s, e);     // as - at
                        float2 d = upk(d2);
                        float x0 = fabsf(d.x), x1 = fabsf(d.y);
                        float y0 = fminf(x0, 1.f), y1 = fminf(x1, 1.f);
                        float t0 = fmaf(y0, -0.5f, x0);
                        float t1 = fmaf(y1, -0.5f, x1);
                        acc0 = fmaf(y0, t0, acc0);
                        acc1 = fmaf(y1, t1, acc1);
                    }
                }
            }
            __syncthreads();
        }

        float w = (c_TA[tile] == c_TB[tile]) ? 1.f : 2.f;
        wacc = fmaf(w, acc0 + acc1, wacc);
        tile++;
        i = 0;
    }

    // block reduction
    red[tid] = wacc;
    __syncthreads();
#pragma unroll
    for (int s = 128; s > 0; s >>= 1) {
        if (tid < s) red[tid] += red[tid + s];
        __syncthreads();
    }
    if (tid == 0) {
        atomicAdd(&g_sum, (double)red[0]);
        __threadfence();
        int t = atomicAdd(&g_cnt, 1);
        if (t == NBLK - 1) {
            double v = atomicAdd(&g_sum, 0.0);
            double n3 = (double)N * (double)N * (double)N;
            out[0] = (float)(v / n3);
            // reset counters for the next graph replay
            __threadfence();
            g_cnt = 0;
            *((volatile int*)&g_bar1) = 0;
            *((volatile int*)&g_bar2) = 0;
        }
    }
}

// ---------------------------------------------------------------------------
extern "C" void kernel_launch(void* const* d_in, const int* in_sizes, int n_in,
                              void* d_out, int out_size) {
    const float* student = (const float*)d_in[0];
    const float* teacher = (const float*)d_in[1];
    float* out = (float*)d_out;

    rkd_fused_kernel<<<NBLK, 256>>>(student, teacher, out);
}

// round 14
// speedup vs baseline: 1.1251x; 1.1251x over previous
#include <cuda_runtime.h>

#define N 384
#define D 256
#define EPSF 1e-12f
#define NTILES 21
#define NUNITS (NTILES * N)   // 8064
#define NBLK 296              // 148 SMs x 2 blocks, all co-resident
#define NGRAM 144             // gram tile-units: 72 per side (6 x 12)
#define BI 8                  // i-batch staged in smem

typedef unsigned long long u64;

// scratch (no allocation allowed)
__device__ float  g_Gs[N * N];
__device__ float  g_Gt[N * N];
__device__ float  g_ps[N * N];     // p_s
__device__ float  g_cps[N * N];    // (Gs_ii - Gs_ij) * p_s
__device__ float  g_nrqs[N * N];   // -Gs_ij * p_s
__device__ float  g_pt[N * N];     // p_t           (j-side)
__device__ float  g_cpt[N * N];    // (Gt_ii - Gt_ij) * p_t (j-side)
__device__ float  g_qtn[N * N];    // -p_t          (k-side, negated)
__device__ float  g_ntn[N * N];    // +Gt_ij * p_t  (k-side, negated nr)
__device__ double g_sum;
__device__ int    g_cnt;
__device__ int    g_bar;

// upper-triangle 64x64 tile enumeration (a <= b), 21 tiles over a 6x6 grid
__constant__ int c_TA[NTILES] = {0,0,0,0,0,0,1,1,1,1,1,2,2,2,2,3,3,3,4,4,5};
__constant__ int c_TB[NTILES] = {0,1,2,3,4,5,1,2,3,4,5,2,3,4,5,3,4,5,4,5,5};

// ---------------------------------------------------------------------------
// packed f32x2 helpers (sm_103a)
__device__ __forceinline__ u64 pk(float lo, float hi) {
    union { float2 f; u64 u; } t; t.f.x = lo; t.f.y = hi; return t.u;
}
__device__ __forceinline__ float2 upk(u64 v) {
    union { float2 f; u64 u; } t; t.u = v; return t.f;
}
union F4U2 { float4 f; ulonglong2 u; };

__device__ __forceinline__ u64 mul2(u64 a, u64 b) {
    u64 r; asm("mul.rn.f32x2 %0,%1,%2;" : "=l"(r) : "l"(a), "l"(b)); return r;
}
__device__ __forceinline__ u64 fma2(u64 a, u64 b, u64 c) {
    u64 r; asm("fma.rn.f32x2 %0,%1,%2,%3;" : "=l"(r) : "l"(a), "l"(b), "l"(c)); return r;
}

// smem buffer shared by both phases
#define SM_AS 0                      // 2*32*34*4 = 8704
#define SM_BS 8704                   // 2*32*68*4 = 17408 -> 26112
#define SM_DA 26112                  // 32*4
#define SM_DB 26240                  // 64*4 -> 26496
#define SM_STAGE 0                   // 8*BI*64*4 = 16384
#define SM_RED 16384                 // 256*4
#define SM_BYTES 26624

// ---------------------------------------------------------------------------
__global__ void __launch_bounds__(256, 2) rkd_fused_kernel(const float* __restrict__ S,
                                                           const float* __restrict__ T,
                                                           float* __restrict__ out) {
    __shared__ __align__(16) char smbuf[SM_BYTES];

    int tid = threadIdx.x;
    int b = blockIdx.x;

    // =======================================================================
    // Phase 1: gram + prep (blocks 0..NGRAM-1, one 32x64 tile each)
    // =======================================================================
    if (b < NGRAM) {
        int z = b / 72;            // 0: student, 1: teacher
        int lin = b - z * 72;      // 0..71
        int bx = lin % 6;          // k-tile (64 wide), 0..5
        int by = lin / 6;          // j-tile (32 tall), 0..11

        const float* __restrict__ E = (z == 0) ? S : T;
        float* __restrict__ G  = (z == 0) ? g_Gs   : g_Gt;
        float* __restrict__ P  = (z == 0) ? g_ps   : g_pt;
        float* __restrict__ CP = (z == 0) ? g_cps  : g_cpt;

        typedef float (*AsT)[32][34];
        typedef float (*BsT)[32][68];
        AsT As = (AsT)(smbuf + SM_AS);
        BsT Bs = (BsT)(smbuf + SM_BS);
        float* dA = (float*)(smbuf + SM_DA);
        float* dB = (float*)(smbuf + SM_DB);

        if (b == 0 && tid == 0) g_sum = 0.0;

        int ty = tid >> 4, tx = tid & 15;
        int row = tid >> 3;
        int c4 = (tid & 7) * 4;

        int tj = by * 32, tk = bx * 64;

        const float* pA  = &E[(tj + row) * D + c4];
        const float* pB0 = &E[(tk + row) * D + c4];
        const float* pB1 = &E[(tk + 32 + row) * D + c4];

        float acc[2][4];
#pragma unroll
        for (int r = 0; r < 2; r++)
#pragma unroll
            for (int c = 0; c < 4; c++) acc[r][c] = 0.f;

        float ssA = 0.f, ssB0 = 0.f, ssB1 = 0.f;

        float4 av  = *reinterpret_cast<const float4*>(pA);
        float4 bv0 = *reinterpret_cast<const float4*>(pB0);
        float4 bv1 = *reinterpret_cast<const float4*>(pB1);
        As[0][c4 + 0][row] = av.x;  As[0][c4 + 1][row] = av.y;
        As[0][c4 + 2][row] = av.z;  As[0][c4 + 3][row] = av.w;
        Bs[0][c4 + 0][row] = bv0.x; Bs[0][c4 + 1][row] = bv0.y;
        Bs[0][c4 + 2][row] = bv0.z; Bs[0][c4 + 3][row] = bv0.w;
        Bs[0][c4 + 0][row + 32] = bv1.x; Bs[0][c4 + 1][row + 32] = bv1.y;
        Bs[0][c4 + 2][row + 32] = bv1.z; Bs[0][c4 + 3][row + 32] = bv1.w;
        ssA  = fmaf(av.x,  av.x,  fmaf(av.y,  av.y,  fmaf(av.z,  av.z,  fmaf(av.w,  av.w,  ssA))));
        ssB0 = fmaf(bv0.x, bv0.x, fmaf(bv0.y, bv0.y, fmaf(bv0.z, bv0.z, fmaf(bv0.w, bv0.w, ssB0))));
        ssB1 = fmaf(bv1.x, bv1.x, fmaf(bv1.y, bv1.y, fmaf(bv1.z, bv1.z, fmaf(bv1.w, bv1.w, ssB1))));
        __syncthreads();

#pragma unroll
        for (int chunk = 0; chunk < D / 32; chunk++) {
            int cur = chunk & 1;
            bool more = (chunk < D / 32 - 1);
            if (more) {
                int off = (chunk + 1) * 32;
                av  = *reinterpret_cast<const float4*>(pA  + off);
                bv0 = *reinterpret_cast<const float4*>(pB0 + off);
                bv1 = *reinterpret_cast<const float4*>(pB1 + off);
            }
#pragma unroll
            for (int kk = 0; kk < 32; kk++) {
                float2 a2 = *reinterpret_cast<const float2*>(&As[cur][kk][ty * 2]);
                float4 b4 = *reinterpret_cast<const float4*>(&Bs[cur][kk][tx * 4]);
                acc[0][0] = fmaf(a2.x, b4.x, acc[0][0]);
                acc[0][1] = fmaf(a2.x, b4.y, acc[0][1]);
                acc[0][2] = fmaf(a2.x, b4.z, acc[0][2]);
                acc[0][3] = fmaf(a2.x, b4.w, acc[0][3]);
                acc[1][0] = fmaf(a2.y, b4.x, acc[1][0]);
                acc[1][1] = fmaf(a2.y, b4.y, acc[1][1]);
                acc[1][2] = fmaf(a2.y, b4.z, acc[1][2]);
                acc[1][3] = fmaf(a2.y, b4.w, acc[1][3]);
            }
            if (more) {
                int nb = cur ^ 1;
                As[nb][c4 + 0][row] = av.x;  As[nb][c4 + 1][row] = av.y;
                As[nb][c4 + 2][row] = av.z;  As[nb][c4 + 3][row] = av.w;
                Bs[nb][c4 + 0][row] = bv0.x; Bs[nb][c4 + 1][row] = bv0.y;
                Bs[nb][c4 + 2][row] = bv0.z; Bs[nb][c4 + 3][row] = bv0.w;
                Bs[nb][c4 + 0][row + 32] = bv1.x; Bs[nb][c4 + 1][row + 32] = bv1.y;
                Bs[nb][c4 + 2][row + 32] = bv1.z; Bs[nb][c4 + 3][row + 32] = bv1.w;
                ssA  = fmaf(av.x,  av.x,  fmaf(av.y,  av.y,  fmaf(av.z,  av.z,  fmaf(av.w,  av.w,  ssA))));
                ssB0 = fmaf(bv0.x, bv0.x, fmaf(bv0.y, bv0.y, fmaf(bv0.z, bv0.z, fmaf(bv0.w, bv0.w, ssB0))));
                ssB1 = fmaf(bv1.x, bv1.x, fmaf(bv1.y, bv1.y, fmaf(bv1.z, bv1.z, fmaf(bv1.w, bv1.w, ssB1))));
            }
            __syncthreads();
        }

#pragma unroll
        for (int m = 4; m > 0; m >>= 1) {
            ssA  += __shfl_xor_sync(0xffffffffu, ssA,  m, 8);
            ssB0 += __shfl_xor_sync(0xffffffffu, ssB0, m, 8);
            ssB1 += __shfl_xor_sync(0xffffffffu, ssB1, m, 8);
        }
        if ((tid & 7) == 0) {
            dA[row] = ssA;
            dB[row] = ssB0;
            dB[row + 32] = ssB1;
        }
        __syncthreads();

        int jg = tj + ty * 2;
        int kg = tk + tx * 4;
#pragma unroll
        for (int r = 0; r < 2; r++) {
            int ig = jg + r;
            float di = dA[ty * 2 + r];

            float p[4], cp[4], nr[4];
#pragma unroll
            for (int c = 0; c < 4; c++) {
                float gij = acc[r][c];
                float dj = dB[tx * 4 + c];
                float cs = di - gij;
                float n2 = fmaxf((dj - gij) + cs, 0.f);
                float pv = (ig == kg + c) ? 0.f : (1.f / fmaxf(sqrtf(n2), EPSF));
                p[c] = pv;
                cp[c] = cs * pv;
                nr[c] = -gij * pv;
            }
            *reinterpret_cast<float4*>(&G[ig * N + kg]) =
                make_float4(acc[r][0], acc[r][1], acc[r][2], acc[r][3]);
            *reinterpret_cast<float4*>(&P[ig * N + kg])  = make_float4(p[0], p[1], p[2], p[3]);
            *reinterpret_cast<float4*>(&CP[ig * N + kg]) = make_float4(cp[0], cp[1], cp[2], cp[3]);
            if (z == 0) {
                *reinterpret_cast<float4*>(&g_nrqs[ig * N + kg]) =
                    make_float4(nr[0], nr[1], nr[2], nr[3]);
            } else {
                *reinterpret_cast<float4*>(&g_qtn[ig * N + kg]) =
                    make_float4(-p[0], -p[1], -p[2], -p[3]);
                *reinterpret_cast<float4*>(&g_ntn[ig * N + kg]) =
                    make_float4(-nr[0], -nr[1], -nr[2], -nr[3]);
            }
        }

        // arrive at grid barrier
        __syncthreads();
        if (tid == 0) {
            __threadfence();
            atomicAdd(&g_bar, 1);
        }
    }

    // =======================================================================
    // Grid barrier: wait until all NGRAM gram blocks have published.
    // All NBLK blocks are co-resident (occ 2), so spinning is safe.
    // =======================================================================
    if (tid == 0) {
        while (*((volatile int*)&g_bar) < NGRAM) __nanosleep(64);
        __threadfence();
    }
    __syncthreads();

    // =======================================================================
    // Phase 2: angle loss (all blocks). 6-packed-op math via negated teacher:
    //   d = qs*(ps*Gs+cps) + qtn*(pt*Gt+cpt) + (ntn*pt + ns*ps)
    // =======================================================================
    typedef float (*StT)[BI][64];
    StT stage = (StT)(smbuf + SM_STAGE);
    float* red = (float*)(smbuf + SM_RED);

    int ty = tid >> 4, tx = tid & 15;

    int jl_col4 = (tid & 15) * 4;
    int l_ii    = (tid >> 4) & 7;
    int l_hi    = tid >> 7;

    int u0 = (b * NUNITS) / NBLK;
    int u1 = ((b + 1) * NUNITS) / NBLK;
    int tile = u0 / N;
    int i = u0 - tile * N;
    int remaining = u1 - u0;

    float wacc = 0.f;

    while (remaining > 0) {
        int cnt = min(N - i, remaining);
        remaining -= cnt;

        int tj = c_TA[tile] * 64;
        int tk = c_TB[tile] * 64;
        int jq = tj + ty * 4;
        int kq = tk + tx * 4;

        const float* src0 = (l_hi ? g_cps  + tj : g_ps  + tj) + jl_col4;  // st 0/1
        const float* src1 = (l_hi ? g_nrqs + tk : g_ps  + tk) + jl_col4;  // st 2/3
        const float* src2 = (l_hi ? g_cpt  + tj : g_pt  + tj) + jl_col4;  // st 4/5
        const float* src3 = (l_hi ? g_ntn  + tk : g_qtn + tk) + jl_col4;  // st 6/7

        // G microtile packed along k (free reinterpret of LDG.128)
        u64 G2s[4][2], G2t[4][2];
#pragma unroll
        for (int jj = 0; jj < 4; jj++) {
            ulonglong2 vs = *reinterpret_cast<const ulonglong2*>(&g_Gs[(jq + jj) * N + kq]);
            ulonglong2 vt = *reinterpret_cast<const ulonglong2*>(&g_Gt[(jq + jj) * N + kq]);
            G2s[jj][0] = vs.x; G2s[jj][1] = vs.y;
            G2t[jj][0] = vt.x; G2t[jj][1] = vt.y;
        }

        float acc0 = 0.f, acc1 = 0.f;

        for (int s = 0; s < cnt; s += BI) {
            {
                int ir = min(i + s + l_ii, N - 1) * N;
                float4 v0 = *reinterpret_cast<const float4*>(src0 + ir);
                float4 v1 = *reinterpret_cast<const float4*>(src1 + ir);
                float4 v2 = *reinterpret_cast<const float4*>(src2 + ir);
                float4 v3 = *reinterpret_cast<const float4*>(src3 + ir);
                *reinterpret_cast<float4*>(&stage[0 + l_hi][l_ii][jl_col4]) = v0;
                *reinterpret_cast<float4*>(&stage[2 + l_hi][l_ii][jl_col4]) = v1;
                *reinterpret_cast<float4*>(&stage[4 + l_hi][l_ii][jl_col4]) = v2;
                *reinterpret_cast<float4*>(&stage[6 + l_hi][l_ii][jl_col4]) = v3;
            }
            __syncthreads();

            int bi = min(BI, cnt - s);
            for (int ii = 0; ii < bi; ii++) {
                float4 pj_s = *reinterpret_cast<const float4*>(&stage[0][ii][ty * 4]);
                float4 cj_s = *reinterpret_cast<const float4*>(&stage[1][ii][ty * 4]);
                F4U2 qk_s;  qk_s.f  = *reinterpret_cast<const float4*>(&stage[2][ii][tx * 4]);
                F4U2 nr_s;  nr_s.f  = *reinterpret_cast<const float4*>(&stage[3][ii][tx * 4]);
                float4 pj_t = *reinterpret_cast<const float4*>(&stage[4][ii][ty * 4]);
                float4 cj_t = *reinterpret_cast<const float4*>(&stage[5][ii][ty * 4]);
                F4U2 qk_tn; qk_tn.f = *reinterpret_cast<const float4*>(&stage[6][ii][tx * 4]);
                F4U2 nr_tn; nr_tn.f = *reinterpret_cast<const float4*>(&stage[7][ii][tx * 4]);

                u64 q2s[2]  = { qk_s.u.x,  qk_s.u.y  };
                u64 n2s[2]  = { nr_s.u.x,  nr_s.u.y  };
                u64 q2tn[2] = { qk_tn.u.x, qk_tn.u.y };
                u64 n2tn[2] = { nr_tn.u.x, nr_tn.u.y };

                float pjs_a[4] = {pj_s.x, pj_s.y, pj_s.z, pj_s.w};
                float cjs_a[4] = {cj_s.x, cj_s.y, cj_s.z, cj_s.w};
                float pjt_a[4] = {pj_t.x, pj_t.y, pj_t.z, pj_t.w};
                float cjt_a[4] = {cj_t.x, cj_t.y, cj_t.z, cj_t.w};

#pragma unroll
                for (int jj = 0; jj < 4; jj++) {
                    u64 p2s = pk(pjs_a[jj], pjs_a[jj]);
                    u64 c2s = pk(cjs_a[jj], cjs_a[jj]);
                    u64 p2t = pk(pjt_a[jj], pjt_a[jj]);
                    u64 c2t = pk(cjt_a[jj], cjt_a[jj]);
#pragma unroll
                    for (int p = 0; p < 2; p++) {
                        u64 t2s = fma2(p2s, G2s[jj][p], c2s);
                        u64 t2t = fma2(p2t, G2t[jj][p], c2t);
                        u64 m   = mul2(n2s[p], p2s);
                        u64 m2  = fma2(n2tn[p], p2t, m);
                        u64 e   = fma2(q2tn[p], t2t, m2);
                        u64 d2  = fma2(q2s[p], t2s, e);     // as - at
                        float2 d = upk(d2);
                        float x0 = fabsf(d.x), x1 = fabsf(d.y);
                        float y0 = fminf(x0, 1.f), y1 = fminf(x1, 1.f);
                        float t0 = fmaf(y0, -0.5f, x0);
                        float t1 = fmaf(y1, -0.5f, x1);
                        acc0 = fmaf(y0, t0, acc0);
                        acc1 = fmaf(y1, t1, acc1);
                    }
                }
            }
            __syncthreads();
        }

        float w = (c_TA[tile] == c_TB[tile]) ? 1.f : 2.f;
        wacc = fmaf(w, acc0 + acc1, wacc);
        tile++;
        i = 0;
    }

    // block reduction
    red[tid] = wacc;
    __syncthreads();
#pragma unroll
    for (int s = 128; s > 0; s >>= 1) {
        if (tid < s) red[tid] += red[tid + s];
        __syncthreads();
    }
    if (tid == 0) {
        atomicAdd(&g_sum, (double)red[0]);
        __threadfence();
        int t = atomicAdd(&g_cnt, 1);
        if (t == NBLK - 1) {
            double v = atomicAdd(&g_sum, 0.0);
            double n3 = (double)N * (double)N * (double)N;
            out[0] = (float)(v / n3);
            // reset counters for the next graph replay
            __threadfence();
            g_cnt = 0;
            *((volatile int*)&g_bar) = 0;
        }
    }
}

// ---------------------------------------------------------------------------
extern "C" void kernel_launch(void* const* d_in, const int* in_sizes, int n_in,
                              void* d_out, int out_size) {
    const float* student = (const float*)d_in[0];
    const float* teacher = (const float*)d_in[1];
    float* out = (float*)d_out;

    rkd_fused_kernel<<<NBLK, 256>>>(student, teacher, out);
}